// round 15
// baseline (speedup 1.0000x reference)
#include <cuda_runtime.h>
#include <cuda_fp16.h>
#include <cstdint>

// B=4, S=2048, PAST=2048, L=4096, D=2048, DFF=8192
// All GEMMs: C = A[M,K] @ B[N,K]^T (+bias), operands pre-split fp16 hi/lo.
// CTA tile 128x256, 8 warps (2x4), warp tile 64x64, 3-stage cp.async ring.

// fp32 scratch
static __device__ float g_scores[33554432];  // [4,2048,4096] pre-softmax
// fp16 hi/lo planes
static __device__ __half g_xh[16777216], g_xl[16777216];          // x [8192,2048]
static __device__ __half g_wqh[4194304], g_wql[4194304];          // Wq^T [2048,2048]
static __device__ __half g_wkh[4194304], g_wkl[4194304];
static __device__ __half g_wvh[4194304], g_wvl[4194304];
static __device__ __half g_wfh[16777216], g_wfl[16777216];        // Wff^T [8192,2048]
static __device__ __half g_woh[16777216], g_wol[16777216];        // Wout^T [2048,8192]
static __device__ __half g_qh[16777216], g_ql[16777216];          // q [4,2048,2048]
static __device__ __half g_kh[33554432], g_kl[33554432];          // k [4,4096,2048]
static __device__ __half g_vth[33554432], g_vtl[33554432];        // V^T [4,2048,4096]
static __device__ __half g_sh[33554432], g_sl[33554432];          // attn [4,2048,4096]
static __device__ __half g_ch[16777216], g_cl[16777216];          // ctx [4,2048,2048]
static __device__ __half g_fh[67108864], g_fl[67108864];          // ff [8192,8192]

__device__ __forceinline__ uint32_t smem_u32(const void* p) {
  uint32_t a;
  asm("{ .reg .u64 t; cvta.to.shared.u64 t, %1; cvt.u32.u64 %0, t; }" : "=r"(a) : "l"(p));
  return a;
}
__device__ __forceinline__ void mma16(float* c, const unsigned* a, const unsigned* b) {
  asm volatile(
      "mma.sync.aligned.m16n8k16.row.col.f32.f16.f16.f32 "
      "{%0,%1,%2,%3}, {%4,%5,%6,%7}, {%8,%9}, {%0,%1,%2,%3};\n"
      : "+f"(c[0]), "+f"(c[1]), "+f"(c[2]), "+f"(c[3])
      : "r"(a[0]), "r"(a[1]), "r"(a[2]), "r"(a[3]), "r"(b[0]), "r"(b[1]));
}
__device__ __forceinline__ void ldsm4(unsigned* r, uint32_t a) {
  asm volatile("ldmatrix.sync.aligned.m8n8.x4.shared.b16 {%0,%1,%2,%3}, [%4];"
               : "=r"(r[0]), "=r"(r[1]), "=r"(r[2]), "=r"(r[3]) : "r"(a));
}
#define CP_ASYNC16(dst, src) \
  asm volatile("cp.async.cg.shared.global [%0], [%1], 16;" :: "r"(dst), "l"(src))
#define CP_COMMIT asm volatile("cp.async.commit_group;" ::: "memory")

__device__ __forceinline__ void split2h(float x, float y, unsigned& hi, unsigned& lo) {
  __half2 h = __floats2half2_rn(x, y);
  __half2 l = __floats2half2_rn(x - __half2float(h.x), y - __half2float(h.y));
  hi = *(unsigned*)&h;
  lo = *(unsigned*)&l;
}

// ===== fp16x3 NT GEMM: 128x256 tile, cp.async 3-stage, ldmatrix fragments =====
// stage layout (80B row stride, 64B used): Ahi[0], Alo[10240], Bhi[20480], Blo[40960]
template <bool EMIT>
__global__ void __launch_bounds__(256) gemm_h(
    const __half* __restrict__ Ah, const __half* __restrict__ Al,
    const __half* __restrict__ Bh, const __half* __restrict__ Bl,
    const float* __restrict__ bias, float* __restrict__ C,
    __half* __restrict__ Ch, __half* __restrict__ Cl,
    int M, int N, int K,
    long long sAz, long long sBz, long long sCz,
    int row_div, long long row_stride) {
  constexpr int STG = 61440;  // (2*128 + 2*256) rows * 80B
  extern __shared__ char smem[];
  const uint32_t sbase = smem_u32(smem);

  const int tid = threadIdx.x;
  const int lane = tid & 31;
  const int wid = tid >> 5;
  const int wm0 = (wid & 1) * 64;   // 2 M-groups
  const int wn0 = (wid >> 1) * 64;  // 4 N-groups
  const int m0 = blockIdx.y * 128;
  const int n0 = blockIdx.x * 256;

  Ah += (long long)blockIdx.z * sAz;
  Al += (long long)blockIdx.z * sAz;
  Bh += (long long)blockIdx.z * sBz;
  Bl += (long long)blockIdx.z * sBz;
  if (C) C += (long long)blockIdx.z * sCz;
  if (EMIT) {
    Ch += (long long)blockIdx.z * sCz;
    Cl += (long long)blockIdx.z * sCz;
  }

  // ldmatrix lane addressing (80B row stride -> conflict-free)
  const int a_r = ((lane >> 3) & 1) * 8 + (lane & 7);
  const int a_k = (lane >> 4) * 16;
  uint32_t aoff[4];
#pragma unroll
  for (int mt = 0; mt < 4; mt++) aoff[mt] = (wm0 + mt * 16 + a_r) * 80 + a_k;
  const int b_r = ((lane >> 4) & 1) * 8 + (lane & 7);
  const int b_k = ((lane >> 3) & 1) * 16;
  uint32_t boff[4];
#pragma unroll
  for (int g = 0; g < 4; g++) boff[g] = (wn0 + g * 16 + b_r) * 80 + b_k;

  float acc[4][8][4];
#pragma unroll
  for (int i = 0; i < 4; i++)
#pragma unroll
    for (int j = 0; j < 8; j++)
#pragma unroll
      for (int l = 0; l < 4; l++) acc[i][j][l] = 0.f;

  auto issue = [&](int st) {
    const int kt = st * 32;
    const uint32_t db = sbase + (uint32_t)(st % 3) * STG;
#pragma unroll
    for (int i = 0; i < 12; i++) {  // 3072 16B-chunks / 256 threads
      const int idx = tid + i * 256;
      if (idx < 1024) {  // A planes: 2 x 128 rows x 4 chunks
        const int plane = idx >> 9, rem = idx & 511, row = rem >> 2, cc = rem & 3;
        const __half* src =
            (plane ? Al : Ah) + (long long)(m0 + row) * K + kt + cc * 8;
        CP_ASYNC16(db + (uint32_t)plane * 10240 + (uint32_t)(row * 80 + cc * 16), src);
      } else {  // B planes: 2 x 256 rows x 4 chunks
        const int j = idx - 1024;
        const int plane = j >> 10, rem = j & 1023, row = rem >> 2, cc = rem & 3;
        const __half* src =
            (plane ? Bl : Bh) + (long long)(n0 + row) * K + kt + cc * 8;
        CP_ASYNC16(db + 20480u + (uint32_t)plane * 20480 +
                       (uint32_t)(row * 80 + cc * 16),
                   src);
      }
    }
  };

  const int T = K >> 5;
  issue(0); CP_COMMIT;
  issue(1); CP_COMMIT;

  for (int t = 0; t < T; ++t) {
    asm volatile("cp.async.wait_group 1;" ::: "memory");
    __syncthreads();
    const uint32_t base = sbase + (uint32_t)(t % 3) * STG;

#pragma unroll
    for (int c = 0; c < 2; c++) {  // two k16 chunks per 32-k stage
      unsigned ah[4][4], al[4][4], bh[4][4], bl[4][4];
#pragma unroll
      for (int mt = 0; mt < 4; mt++) ldsm4(ah[mt], base + aoff[mt] + c * 32);
#pragma unroll
      for (int mt = 0; mt < 4; mt++) ldsm4(al[mt], base + 10240 + aoff[mt] + c * 32);
#pragma unroll
      for (int g = 0; g < 4; g++) ldsm4(bh[g], base + 20480 + boff[g] + c * 32);
#pragma unroll
      for (int g = 0; g < 4; g++) ldsm4(bl[g], base + 40960 + boff[g] + c * 32);
      // pass-major: dependent MMAs on one accumulator are 32 apart
#pragma unroll
      for (int mt = 0; mt < 4; mt++)
#pragma unroll
        for (int nt = 0; nt < 8; nt++)
          mma16(acc[mt][nt], ah[mt], &bh[nt >> 1][(nt & 1) * 2]);
#pragma unroll
      for (int mt = 0; mt < 4; mt++)
#pragma unroll
        for (int nt = 0; nt < 8; nt++)
          mma16(acc[mt][nt], al[mt], &bh[nt >> 1][(nt & 1) * 2]);
#pragma unroll
      for (int mt = 0; mt < 4; mt++)
#pragma unroll
        for (int nt = 0; nt < 8; nt++)
          mma16(acc[mt][nt], ah[mt], &bl[nt >> 1][(nt & 1) * 2]);
    }

    if (t + 2 < T) issue(t + 2);
    CP_COMMIT;  // empty groups in tail keep wait arithmetic uniform
  }
  asm volatile("cp.async.wait_group 0;" ::: "memory");

  // epilogue with optional fp32 store and optional hi/lo emit
  const long long roff =
      (long long)(m0 / row_div) * row_stride + (long long)(m0 % row_div) * N;
  float* Cb = C ? C + roff : nullptr;
  __half* Chb = EMIT ? Ch + roff : nullptr;
  __half* Clb = EMIT ? Cl + roff : nullptr;
  const int qq = lane >> 2, rr = lane & 3;
#pragma unroll
  for (int mt = 0; mt < 4; mt++) {
    const int r0 = wm0 + mt * 16 + qq;
#pragma unroll
    for (int nt = 0; nt < 8; nt++) {
      const int gc = n0 + wn0 + nt * 8 + rr * 2;
      float bv0 = 0.f, bv1 = 0.f;
      if (bias) {
        bv0 = bias[gc];
        bv1 = bias[gc + 1];
      }
      float2 v0, v1;
      v0.x = acc[mt][nt][0] + bv0;
      v0.y = acc[mt][nt][1] + bv1;
      v1.x = acc[mt][nt][2] + bv0;
      v1.y = acc[mt][nt][3] + bv1;
      if (Cb) {
        *(float2*)(Cb + (long long)r0 * N + gc) = v0;
        *(float2*)(Cb + (long long)(r0 + 8) * N + gc) = v1;
      }
      if (EMIT) {
        unsigned hh, ll;
        split2h(v0.x, v0.y, hh, ll);
        *(unsigned*)(Chb + (long long)r0 * N + gc) = hh;
        *(unsigned*)(Clb + (long long)r0 * N + gc) = ll;
        split2h(v1.x, v1.y, hh, ll);
        *(unsigned*)(Chb + (long long)(r0 + 8) * N + gc) = hh;
        *(unsigned*)(Clb + (long long)(r0 + 8) * N + gc) = ll;
      }
    }
  }
}

// elementwise fp32 -> fp16 hi/lo
__global__ void split_ew(const float* __restrict__ s, __half* __restrict__ h,
                         __half* __restrict__ l) {
  const long long i = (long long)blockIdx.x * blockDim.x + threadIdx.x;
  const float4 v = ((const float4*)s)[i];
  unsigned h0, l0, h1, l1;
  split2h(v.x, v.y, h0, l0);
  split2h(v.z, v.w, h1, l1);
  ((uint2*)h)[i] = make_uint2(h0, h1);
  ((uint2*)l)[i] = make_uint2(l0, l1);
}

// fp32 [R][C] -> fp16 hi/lo transposed [C][R]; batched via z
__global__ void split_tr(const float* __restrict__ src, __half* __restrict__ hT,
                         __half* __restrict__ lT, int R, int C, long long szs,
                         long long szd) {
  __shared__ float t[32][33];
  src += (long long)blockIdx.z * szs;
  hT += (long long)blockIdx.z * szd;
  lT += (long long)blockIdx.z * szd;
  const int c0 = blockIdx.x * 32, r0 = blockIdx.y * 32;
  for (int j = threadIdx.y; j < 32; j += 8)
    t[j][threadIdx.x] = src[(long long)(r0 + j) * C + c0 + threadIdx.x];
  __syncthreads();
  for (int j = threadIdx.y; j < 32; j += 8) {
    const float v = t[threadIdx.x][j];
    const __half h = __float2half_rn(v);
    const __half l = __float2half_rn(v - __half2float(h));
    const long long o = (long long)(c0 + j) * R + r0 + threadIdx.x;
    hT[o] = h;
    lT[o] = l;
  }
}

// k cache: fp32 copy into rows [0,2048) of [4,4096,2048] + hi/lo emit
__global__ void copy_cache_k(const float* __restrict__ src, float* __restrict__ dst,
                             __half* __restrict__ kh, __half* __restrict__ kl) {
  const long long i = (long long)blockIdx.x * blockDim.x + threadIdx.x;
  const long long per_b = 2048LL * 512;
  const int b = (int)(i / per_b);
  const long long rem = i - (long long)b * per_b;
  const long long o = (long long)b * 4096 * 512 + rem;
  const float4 v = ((const float4*)src)[i];
  ((float4*)dst)[o] = v;
  unsigned h0, l0, h1, l1;
  split2h(v.x, v.y, h0, l0);
  split2h(v.z, v.w, h1, l1);
  ((uint2*)kh)[o] = make_uint2(h0, h1);
  ((uint2*)kl)[o] = make_uint2(l0, l1);
}

__global__ void copy_cache(const float* __restrict__ src, float* __restrict__ dst) {
  const long long i = (long long)blockIdx.x * blockDim.x + threadIdx.x;
  const long long per_b = 2048LL * 512;
  const int b = (int)(i / per_b);
  const long long rem = i - (long long)b * per_b;
  ((float4*)dst)[(long long)b * 4096 * 512 + rem] = ((const float4*)src)[i];
}

// softmax over QUERY axis of scores [4,2048,4096]; writes attn as fp16 hi/lo
__global__ void softmax_q_split(const float* __restrict__ s, __half* __restrict__ oh,
                                __half* __restrict__ ol) {
  const int col = blockIdx.x * blockDim.x + threadIdx.x;
  const long long base = (long long)blockIdx.y * 2048 * 4096 + col;
  const float* p = s + base;
  float mx = -1e30f;
#pragma unroll 16
  for (int i = 0; i < 2048; i++) mx = fmaxf(mx, p[(long long)i * 4096]);
  float sum = 0.f;
#pragma unroll 16
  for (int i = 0; i < 2048; i++) sum += __expf(p[(long long)i * 4096] - mx);
  const float inv = 1.f / sum;
#pragma unroll 16
  for (int i = 0; i < 2048; i++) {
    const float a = __expf(p[(long long)i * 4096] - mx) * inv;
    const long long o = base + (long long)i * 4096;
    const __half h = __float2half_rn(a);
    oh[o] = h;
    ol[o] = __float2half_rn(a - __half2float(h));
  }
}

extern "C" void kernel_launch(void* const* d_in, const int* in_sizes, int n_in,
                              void* d_out, int out_size) {
  const float* x = (const float*)d_in[0];
  const float* k_cache = (const float*)d_in[1];
  const float* v_cache = (const float*)d_in[2];
  const float* Wq = (const float*)d_in[3];
  const float* bq = (const float*)d_in[4];
  const float* Wk = (const float*)d_in[5];
  const float* bk = (const float*)d_in[6];
  const float* Wv = (const float*)d_in[7];
  const float* bv = (const float*)d_in[8];
  const float* Wff = (const float*)d_in[9];
  const float* bff = (const float*)d_in[10];
  const float* Wout = (const float*)d_in[11];
  const float* bout = (const float*)d_in[12];

  float* out = (float*)d_out;            // [4,2048,2048]
  float* k_out = out + 16777216LL;       // [4,4096,2048]
  float* v_out = k_out + 33554432LL;     // [4,4096,2048]

  float* sc;
  cudaGetSymbolAddress((void**)&sc, g_scores);
#define SYM(var, sym) __half* var; cudaGetSymbolAddress((void**)&var, sym)
  SYM(xh, g_xh);   SYM(xl, g_xl);
  SYM(wqh, g_wqh); SYM(wql, g_wql);
  SYM(wkh, g_wkh); SYM(wkl, g_wkl);
  SYM(wvh, g_wvh); SYM(wvl, g_wvl);
  SYM(wfh, g_wfh); SYM(wfl, g_wfl);
  SYM(woh, g_woh); SYM(wol, g_wol);
  SYM(qh, g_qh);   SYM(ql, g_ql);
  SYM(kh, g_kh);   SYM(kl, g_kl);
  SYM(vth, g_vth); SYM(vtl, g_vtl);
  SYM(sh, g_sh);   SYM(sl, g_sl);
  SYM(ch, g_ch);   SYM(cl, g_cl);
  SYM(fh, g_fh);   SYM(fl, g_fl);
#undef SYM

  const int SMEM = 3 * 61440;  // 184320
  cudaFuncSetAttribute(gemm_h<false>, cudaFuncAttributeMaxDynamicSharedMemorySize, SMEM);
  cudaFuncSetAttribute(gemm_h<true>, cudaFuncAttributeMaxDynamicSharedMemorySize, SMEM);

  const dim3 blk(256);
  const dim3 t32(32, 8);

  // Launch order arranged so launch #5 (ncu -s 5 -c 1) is the q-proj GEMM.
  copy_cache_k<<<16384, 256>>>(k_cache, k_out, kh, kl);                  // 1
  copy_cache<<<16384, 256>>>(v_cache, v_out);                           // 2
  split_ew<<<16384, 256>>>(x, xh, xl);                                  // 3
  split_tr<<<dim3(64, 64, 1), t32>>>(Wq, wqh, wql, 2048, 2048, 0, 0);   // 4

  // 5: q-proj (profiled) — emit split only
  gemm_h<true><<<dim3(8, 64, 1), blk, SMEM>>>(
      xh, xl, wqh, wql, bq, nullptr, qh, ql,
      8192, 2048, 2048, 0, 0, 0, 8192, 0);

  split_tr<<<dim3(64, 64, 1), t32>>>(Wk, wkh, wkl, 2048, 2048, 0, 0);   // 6
  // k-proj: fp32 into cache rows [2048,4096) + split emit (same remap)
  gemm_h<true><<<dim3(8, 64, 1), blk, SMEM>>>(
      xh, xl, wkh, wkl, bk, k_out + 2048LL * 2048, kh + 2048LL * 2048,
      kl + 2048LL * 2048, 8192, 2048, 2048, 0, 0, 0, 2048, 4096LL * 2048);

  split_tr<<<dim3(64, 64, 1), t32>>>(Wv, wvh, wvl, 2048, 2048, 0, 0);
  // v-proj: fp32 only (split comes from the V^T pass)
  gemm_h<false><<<dim3(8, 64, 1), blk, SMEM>>>(
      xh, xl, wvh, wvl, bv, v_out + 2048LL * 2048, nullptr, nullptr,
      8192, 2048, 2048, 0, 0, 0, 2048, 4096LL * 2048);

  // V^T split per batch: [4096,2048] -> [2048,4096]
  split_tr<<<dim3(64, 128, 4), t32>>>(v_out, vth, vtl, 4096, 2048,
                                      4096LL * 2048, 2048LL * 4096);

  // scores = q @ k^T
  gemm_h<false><<<dim3(16, 16, 4), blk, SMEM>>>(
      qh, ql, kh, kl, nullptr, sc, nullptr, nullptr,
      2048, 4096, 2048, 2048LL * 2048, 4096LL * 2048, 2048LL * 4096, 2048, 0);

  softmax_q_split<<<dim3(16, 4), 256>>>(sc, sh, sl);

  // ctx = attn @ V (B = V^T planes), emit split only
  gemm_h<true><<<dim3(8, 16, 4), blk, SMEM>>>(
      sh, sl, vth, vtl, nullptr, nullptr, ch, cl,
      2048, 2048, 4096, 2048LL * 4096, 2048LL * 4096, 2048LL * 2048, 2048, 0);

  // FFN
  split_tr<<<dim3(256, 64, 1), t32>>>(Wff, wfh, wfl, 2048, 8192, 0, 0);
  gemm_h<true><<<dim3(32, 64, 1), blk, SMEM>>>(
      ch, cl, wfh, wfl, bff, nullptr, fh, fl,
      8192, 8192, 2048, 0, 0, 0, 8192, 0);
  split_tr<<<dim3(64, 256, 1), t32>>>(Wout, woh, wol, 8192, 2048, 0, 0);
  gemm_h<false><<<dim3(8, 64, 1), blk, SMEM>>>(
      fh, fl, woh, wol, bout, out, nullptr, nullptr,
      8192, 2048, 8192, 0, 0, 0, 8192, 0);
}

// round 16
// speedup vs baseline: 1.4445x; 1.4445x over previous
#include <cuda_runtime.h>
#include <cuda_fp16.h>
#include <cstdint>

// B=4, S=2048, PAST=2048, L=4096, D=2048, DFF=8192
// All GEMMs: C = A[M,K] @ B[N,K]^T (+bias), operands pre-split fp16 hi/lo.
// FFN is linear => folded: out = ctx @ (Wff@Wout) + (bff@Wout + bout).

// fp32 scratch
static __device__ float g_scores[33554432];  // [4,2048,4096] pre-softmax
static __device__ float g_b2[2048];          // folded FFN bias
// fp16 hi/lo planes
static __device__ __half g_xh[16777216], g_xl[16777216];          // x [8192,2048]
static __device__ __half g_wqh[4194304], g_wql[4194304];          // Wq^T [2048,2048]
static __device__ __half g_wkh[4194304], g_wkl[4194304];
static __device__ __half g_wvh[4194304], g_wvl[4194304];
static __device__ __half g_wfh[16777216], g_wfl[16777216];        // Wff [2048,8192] (k-contig)
static __device__ __half g_woh[16777216], g_wol[16777216];        // Wout^T [2048,8192]
static __device__ __half g_w2h[4194304], g_w2l[4194304];          // W2^T [2048,2048]
static __device__ __half g_qh[16777216], g_ql[16777216];          // q [4,2048,2048]
static __device__ __half g_kh[33554432], g_kl[33554432];          // k [4,4096,2048]
static __device__ __half g_vth[33554432], g_vtl[33554432];        // V^T [4,2048,4096]
static __device__ __half g_sh[33554432], g_sl[33554432];          // attn [4,2048,4096]
static __device__ __half g_ch[16777216], g_cl[16777216];          // ctx [4,2048,2048]

__device__ __forceinline__ uint32_t smem_u32(const void* p) {
  uint32_t a;
  asm("{ .reg .u64 t; cvta.to.shared.u64 t, %1; cvt.u32.u64 %0, t; }" : "=r"(a) : "l"(p));
  return a;
}
__device__ __forceinline__ void mma16(float* c, const unsigned* a, const unsigned* b) {
  asm volatile(
      "mma.sync.aligned.m16n8k16.row.col.f32.f16.f16.f32 "
      "{%0,%1,%2,%3}, {%4,%5,%6,%7}, {%8,%9}, {%0,%1,%2,%3};\n"
      : "+f"(c[0]), "+f"(c[1]), "+f"(c[2]), "+f"(c[3])
      : "r"(a[0]), "r"(a[1]), "r"(a[2]), "r"(a[3]), "r"(b[0]), "r"(b[1]));
}
__device__ __forceinline__ void ldsm4(unsigned* r, uint32_t a) {
  asm volatile("ldmatrix.sync.aligned.m8n8.x4.shared.b16 {%0,%1,%2,%3}, [%4];"
               : "=r"(r[0]), "=r"(r[1]), "=r"(r[2]), "=r"(r[3]) : "r"(a));
}
#define CP_ASYNC16(dst, src) \
  asm volatile("cp.async.cg.shared.global [%0], [%1], 16;" :: "r"(dst), "l"(src))
#define CP_COMMIT asm volatile("cp.async.commit_group;" ::: "memory")

__device__ __forceinline__ void split2h(float x, float y, unsigned& hi, unsigned& lo) {
  __half2 h = __floats2half2_rn(x, y);
  __half2 l = __floats2half2_rn(x - __half2float(h.x), y - __half2float(h.y));
  hi = *(unsigned*)&h;
  lo = *(unsigned*)&l;
}

// ============ fp16x3 NT GEMM: cp.async 4-stage + ldmatrix fragments ============
// smem per stage: 4 planes (Ahi,Alo,Bhi,Blo) of [128 rows][80B] = 40960B; 4 stages.
template <bool EMIT>
__global__ void __launch_bounds__(256) gemm_h(
    const __half* __restrict__ Ah, const __half* __restrict__ Al,
    const __half* __restrict__ Bh, const __half* __restrict__ Bl,
    const float* __restrict__ bias, float* __restrict__ C,
    __half* __restrict__ Ch, __half* __restrict__ Cl,
    int M, int N, int K,
    long long sAz, long long sBz, long long sCz,
    int row_div, long long row_stride) {
  constexpr int STG = 40960;
  extern __shared__ char smem[];
  const uint32_t sbase = smem_u32(smem);

  const int tid = threadIdx.x;
  const int lane = tid & 31;
  const int wid = tid >> 5;
  const int wm0 = (wid >> 2) * 64;  // 2x4 warp grid, 64x32 warp tiles
  const int wn0 = (wid & 3) * 32;
  const int m0 = blockIdx.y * 128;
  const int n0 = blockIdx.x * 128;

  Ah += (long long)blockIdx.z * sAz;
  Al += (long long)blockIdx.z * sAz;
  Bh += (long long)blockIdx.z * sBz;
  Bl += (long long)blockIdx.z * sBz;
  if (C) C += (long long)blockIdx.z * sCz;
  if (EMIT) {
    Ch += (long long)blockIdx.z * sCz;
    Cl += (long long)blockIdx.z * sCz;
  }

  // per-thread ldmatrix lane addressing (80B row stride -> conflict-free)
  const int a_r = ((lane >> 3) & 1) * 8 + (lane & 7);
  const int a_k = (lane >> 4) * 16;
  uint32_t aoff[4];
#pragma unroll
  for (int mt = 0; mt < 4; mt++) aoff[mt] = (wm0 + mt * 16 + a_r) * 80 + a_k;
  const int b_r = ((lane >> 4) & 1) * 8 + (lane & 7);
  const int b_k = ((lane >> 3) & 1) * 16;
  uint32_t boff[2];
#pragma unroll
  for (int g = 0; g < 2; g++) boff[g] = (wn0 + g * 16 + b_r) * 80 + b_k;

  float acc[4][4][4];
#pragma unroll
  for (int i = 0; i < 4; i++)
#pragma unroll
    for (int j = 0; j < 4; j++)
#pragma unroll
      for (int l = 0; l < 4; l++) acc[i][j][l] = 0.f;

  auto issue = [&](int st) {
    const int kt = st * 32;
    const uint32_t db = sbase + (uint32_t)(st & 3) * STG;
#pragma unroll
    for (int i = 0; i < 8; i++) {  // 2048 16B-chunks / 256 threads
      const int idx = tid + i * 256;
      const int plane = idx >> 9, rem = idx & 511, row = rem >> 2, cc = rem & 3;
      const __half* src = (plane == 0)   ? Ah + (long long)(m0 + row) * K + kt
                          : (plane == 1) ? Al + (long long)(m0 + row) * K + kt
                          : (plane == 2) ? Bh + (long long)(n0 + row) * K + kt
                                         : Bl + (long long)(n0 + row) * K + kt;
      CP_ASYNC16(db + (uint32_t)plane * 10240 + (uint32_t)(row * 80 + cc * 16),
                 src + cc * 8);
    }
  };

  const int T = K >> 5;
  issue(0); CP_COMMIT;
  issue(1); CP_COMMIT;
  issue(2); CP_COMMIT;

  for (int t = 0; t < T; ++t) {
    asm volatile("cp.async.wait_group 2;" ::: "memory");
    __syncthreads();
    const uint32_t base = sbase + (uint32_t)(t & 3) * STG;

#pragma unroll
    for (int c = 0; c < 2; c++) {  // two k16 chunks per 32-k stage
      unsigned ah[4][4], al[4][4], bh[2][4], bl[2][4];
#pragma unroll
      for (int mt = 0; mt < 4; mt++) ldsm4(ah[mt], base + aoff[mt] + c * 32);
#pragma unroll
      for (int mt = 0; mt < 4; mt++) ldsm4(al[mt], base + 10240 + aoff[mt] + c * 32);
      ldsm4(bh[0], base + 20480 + boff[0] + c * 32);
      ldsm4(bh[1], base + 20480 + boff[1] + c * 32);
      ldsm4(bl[0], base + 30720 + boff[0] + c * 32);
      ldsm4(bl[1], base + 30720 + boff[1] + c * 32);
      // pass-major order: dependent MMAs on one accumulator are 16 apart
#pragma unroll
      for (int mt = 0; mt < 4; mt++)
#pragma unroll
        for (int nt = 0; nt < 4; nt++)
          mma16(acc[mt][nt], ah[mt], &bh[nt >> 1][(nt & 1) * 2]);
#pragma unroll
      for (int mt = 0; mt < 4; mt++)
#pragma unroll
        for (int nt = 0; nt < 4; nt++)
          mma16(acc[mt][nt], al[mt], &bh[nt >> 1][(nt & 1) * 2]);
#pragma unroll
      for (int mt = 0; mt < 4; mt++)
#pragma unroll
        for (int nt = 0; nt < 4; nt++)
          mma16(acc[mt][nt], ah[mt], &bl[nt >> 1][(nt & 1) * 2]);
    }

    if (t + 3 < T) issue(t + 3);
    CP_COMMIT;  // empty groups in the tail keep wait arithmetic uniform
  }
  asm volatile("cp.async.wait_group 0;" ::: "memory");

  // epilogue with optional fp32 store and optional hi/lo emit
  const long long roff =
      (long long)(m0 / row_div) * row_stride + (long long)(m0 % row_div) * N;
  float* Cb = C ? C + roff : nullptr;
  __half* Chb = EMIT ? Ch + roff : nullptr;
  __half* Clb = EMIT ? Cl + roff : nullptr;
  const int qq = lane >> 2, rr = lane & 3;
#pragma unroll
  for (int mt = 0; mt < 4; mt++) {
    const int r0 = wm0 + mt * 16 + qq;
#pragma unroll
    for (int nt = 0; nt < 4; nt++) {
      const int gc = n0 + wn0 + nt * 8 + rr * 2;
      float bv0 = 0.f, bv1 = 0.f;
      if (bias) {
        bv0 = bias[gc];
        bv1 = bias[gc + 1];
      }
      float2 v0, v1;
      v0.x = acc[mt][nt][0] + bv0;
      v0.y = acc[mt][nt][1] + bv1;
      v1.x = acc[mt][nt][2] + bv0;
      v1.y = acc[mt][nt][3] + bv1;
      if (Cb) {
        *(float2*)(Cb + (long long)r0 * N + gc) = v0;
        *(float2*)(Cb + (long long)(r0 + 8) * N + gc) = v1;
      }
      if (EMIT) {
        unsigned hh, ll;
        split2h(v0.x, v0.y, hh, ll);
        *(unsigned*)(Chb + (long long)r0 * N + gc) = hh;
        *(unsigned*)(Clb + (long long)r0 * N + gc) = ll;
        split2h(v1.x, v1.y, hh, ll);
        *(unsigned*)(Chb + (long long)(r0 + 8) * N + gc) = hh;
        *(unsigned*)(Clb + (long long)(r0 + 8) * N + gc) = ll;
      }
    }
  }
}

// elementwise fp32 -> fp16 hi/lo
__global__ void split_ew(const float* __restrict__ s, __half* __restrict__ h,
                         __half* __restrict__ l) {
  const long long i = (long long)blockIdx.x * blockDim.x + threadIdx.x;
  const float4 v = ((const float4*)s)[i];
  unsigned h0, l0, h1, l1;
  split2h(v.x, v.y, h0, l0);
  split2h(v.z, v.w, h1, l1);
  ((uint2*)h)[i] = make_uint2(h0, h1);
  ((uint2*)l)[i] = make_uint2(l0, l1);
}

// fp32 [R][C] -> fp16 hi/lo transposed [C][R]; batched via z
__global__ void split_tr(const float* __restrict__ src, __half* __restrict__ hT,
                         __half* __restrict__ lT, int R, int C, long long szs,
                         long long szd) {
  __shared__ float t[32][33];
  src += (long long)blockIdx.z * szs;
  hT += (long long)blockIdx.z * szd;
  lT += (long long)blockIdx.z * szd;
  const int c0 = blockIdx.x * 32, r0 = blockIdx.y * 32;
  for (int j = threadIdx.y; j < 32; j += 8)
    t[j][threadIdx.x] = src[(long long)(r0 + j) * C + c0 + threadIdx.x];
  __syncthreads();
  for (int j = threadIdx.y; j < 32; j += 8) {
    const float v = t[threadIdx.x][j];
    const __half h = __float2half_rn(v);
    const __half l = __float2half_rn(v - __half2float(h));
    const long long o = (long long)(c0 + j) * R + r0 + threadIdx.x;
    hT[o] = h;
    lT[o] = l;
  }
}

// k cache: fp32 copy into rows [0,2048) of [4,4096,2048] + hi/lo emit
__global__ void copy_cache_k(const float* __restrict__ src, float* __restrict__ dst,
                             __half* __restrict__ kh, __half* __restrict__ kl) {
  const long long i = (long long)blockIdx.x * blockDim.x + threadIdx.x;
  const long long per_b = 2048LL * 512;
  const int b = (int)(i / per_b);
  const long long rem = i - (long long)b * per_b;
  const long long o = (long long)b * 4096 * 512 + rem;
  const float4 v = ((const float4*)src)[i];
  ((float4*)dst)[o] = v;
  unsigned h0, l0, h1, l1;
  split2h(v.x, v.y, h0, l0);
  split2h(v.z, v.w, h1, l1);
  ((uint2*)kh)[o] = make_uint2(h0, h1);
  ((uint2*)kl)[o] = make_uint2(l0, l1);
}

__global__ void copy_cache(const float* __restrict__ src, float* __restrict__ dst) {
  const long long i = (long long)blockIdx.x * blockDim.x + threadIdx.x;
  const long long per_b = 2048LL * 512;
  const int b = (int)(i / per_b);
  const long long rem = i - (long long)b * per_b;
  ((float4*)dst)[(long long)b * 4096 * 512 + rem] = ((const float4*)src)[i];
}

// softmax over QUERY axis of scores [4,2048,4096]; writes attn as fp16 hi/lo
__global__ void softmax_q_split(const float* __restrict__ s, __half* __restrict__ oh,
                                __half* __restrict__ ol) {
  const int col = blockIdx.x * blockDim.x + threadIdx.x;
  const long long base = (long long)blockIdx.y * 2048 * 4096 + col;
  const float* p = s + base;
  float mx = -1e30f;
#pragma unroll 16
  for (int i = 0; i < 2048; i++) mx = fmaxf(mx, p[(long long)i * 4096]);
  float sum = 0.f;
#pragma unroll 16
  for (int i = 0; i < 2048; i++) sum += __expf(p[(long long)i * 4096] - mx);
  const float inv = 1.f / sum;
#pragma unroll 16
  for (int i = 0; i < 2048; i++) {
    const float a = __expf(p[(long long)i * 4096] - mx) * inv;
    const long long o = base + (long long)i * 4096;
    const __half h = __float2half_rn(a);
    oh[o] = h;
    ol[o] = __float2half_rn(a - __half2float(h));
  }
}

// b2[n] = bout[n] + sum_f bff[f] * Wout[f][n]   (folded FFN bias)
__global__ void fold_bias(const float* __restrict__ bff, const float* __restrict__ Wout,
                          const float* __restrict__ bout, float* __restrict__ b2) {
  const int n = blockIdx.x * blockDim.x + threadIdx.x;  // 2048
  float s = bout[n];
  for (int f = 0; f < 8192; f++) s += bff[f] * Wout[(long long)f * 2048 + n];
  b2[n] = s;
}

extern "C" void kernel_launch(void* const* d_in, const int* in_sizes, int n_in,
                              void* d_out, int out_size) {
  const float* x = (const float*)d_in[0];
  const float* k_cache = (const float*)d_in[1];
  const float* v_cache = (const float*)d_in[2];
  const float* Wq = (const float*)d_in[3];
  const float* bq = (const float*)d_in[4];
  const float* Wk = (const float*)d_in[5];
  const float* bk = (const float*)d_in[6];
  const float* Wv = (const float*)d_in[7];
  const float* bv = (const float*)d_in[8];
  const float* Wff = (const float*)d_in[9];
  const float* bff = (const float*)d_in[10];
  const float* Wout = (const float*)d_in[11];
  const float* bout = (const float*)d_in[12];

  float* out = (float*)d_out;            // [4,2048,2048]
  float* k_out = out + 16777216LL;       // [4,4096,2048]
  float* v_out = k_out + 33554432LL;     // [4,4096,2048]

  float *sc, *b2;
  cudaGetSymbolAddress((void**)&sc, g_scores);
  cudaGetSymbolAddress((void**)&b2, g_b2);
#define SYM(var, sym) __half* var; cudaGetSymbolAddress((void**)&var, sym)
  SYM(xh, g_xh);   SYM(xl, g_xl);
  SYM(wqh, g_wqh); SYM(wql, g_wql);
  SYM(wkh, g_wkh); SYM(wkl, g_wkl);
  SYM(wvh, g_wvh); SYM(wvl, g_wvl);
  SYM(wfh, g_wfh); SYM(wfl, g_wfl);
  SYM(woh, g_woh); SYM(wol, g_wol);
  SYM(w2h, g_w2h); SYM(w2l, g_w2l);
  SYM(qh, g_qh);   SYM(ql, g_ql);
  SYM(kh, g_kh);   SYM(kl, g_kl);
  SYM(vth, g_vth); SYM(vtl, g_vtl);
  SYM(sh, g_sh);   SYM(sl, g_sl);
  SYM(ch, g_ch);   SYM(cl, g_cl);
#undef SYM

  const int SMEM = 4 * 40960;  // 163840
  cudaFuncSetAttribute(gemm_h<false>, cudaFuncAttributeMaxDynamicSharedMemorySize, SMEM);
  cudaFuncSetAttribute(gemm_h<true>, cudaFuncAttributeMaxDynamicSharedMemorySize, SMEM);

  const dim3 blk(256);
  const dim3 t32(32, 8);

  // ncu -s 5 profiles the 6th launch -> make it the q-proj GEMM.
  copy_cache_k<<<16384, 256>>>(k_cache, k_out, kh, kl);                  // 1
  copy_cache<<<16384, 256>>>(v_cache, v_out);                            // 2
  split_ew<<<16384, 256>>>(x, xh, xl);                                   // 3
  split_tr<<<dim3(64, 64, 1), t32>>>(Wq, wqh, wql, 2048, 2048, 0, 0);    // 4
  split_tr<<<dim3(64, 64, 1), t32>>>(Wk, wkh, wkl, 2048, 2048, 0, 0);    // 5

  // 6: q-proj (profiled) — emit split only
  gemm_h<true><<<dim3(16, 64, 1), blk, SMEM>>>(
      xh, xl, wqh, wql, bq, nullptr, qh, ql,
      8192, 2048, 2048, 0, 0, 0, 8192, 0);

  // k-proj: fp32 into cache rows [2048,4096) + split emit (same remap)
  gemm_h<true><<<dim3(16, 64, 1), blk, SMEM>>>(
      xh, xl, wkh, wkl, bk, k_out + 2048LL * 2048, kh + 2048LL * 2048,
      kl + 2048LL * 2048, 8192, 2048, 2048, 0, 0, 0, 2048, 4096LL * 2048);

  split_tr<<<dim3(64, 64, 1), t32>>>(Wv, wvh, wvl, 2048, 2048, 0, 0);
  // v-proj: fp32 only (split comes from the V^T pass)
  gemm_h<false><<<dim3(16, 64, 1), blk, SMEM>>>(
      xh, xl, wvh, wvl, bv, v_out + 2048LL * 2048, nullptr, nullptr,
      8192, 2048, 2048, 0, 0, 0, 2048, 4096LL * 2048);

  // V^T split per batch: [4096,2048] -> [2048,4096]
  split_tr<<<dim3(64, 128, 4), t32>>>(v_out, vth, vtl, 4096, 2048,
                                      4096LL * 2048, 2048LL * 4096);

  // FFN fold: W2^T[n,k] = sum_f WoutT[n,f] * Wff[k,f]  (both k-contiguous)
  split_ew<<<16384, 256>>>(Wff, wfh, wfl);                      // Wff [2048,8192]
  split_tr<<<dim3(64, 256, 1), t32>>>(Wout, woh, wol, 8192, 2048, 0, 0);
  gemm_h<true><<<dim3(16, 16, 1), blk, SMEM>>>(
      woh, wol, wfh, wfl, nullptr, nullptr, w2h, w2l,
      2048, 2048, 8192, 0, 0, 0, 2048, 0);
  fold_bias<<<8, 256>>>(bff, Wout, bout, b2);

  // scores = q @ k^T
  gemm_h<false><<<dim3(32, 16, 4), blk, SMEM>>>(
      qh, ql, kh, kl, nullptr, sc, nullptr, nullptr,
      2048, 4096, 2048, 2048LL * 2048, 4096LL * 2048, 2048LL * 4096, 2048, 0);

  softmax_q_split<<<dim3(16, 4), 256>>>(sc, sh, sl);

  // ctx = attn @ V (B = V^T planes), emit split only
  gemm_h<true><<<dim3(16, 16, 4), blk, SMEM>>>(
      sh, sl, vth, vtl, nullptr, nullptr, ch, cl,
      2048, 2048, 4096, 2048LL * 4096, 2048LL * 4096, 2048LL * 2048, 2048, 0);

  // out = ctx @ W2 + b2  (folded FFN)
  gemm_h<false><<<dim3(16, 64, 1), blk, SMEM>>>(
      ch, cl, w2h, w2l, b2, out, nullptr, nullptr,
      8192, 2048, 2048, 0, 0, 0, 8192, 0);
}